// round 12
// baseline (speedup 1.0000x reference)
#include <cuda_runtime.h>
#include <cuda_fp16.h>
#include <cstdint>

#define Bq 64
#define Hq 1024
#define NG 4096
#define DIN 768
#define TAUD 500
#define Lq 127
#define SEQLEN 128
#define NPB 144       // 128 main + 16 logits

// ---- dynamic smem layout (bytes) ----
// X bufs: 2 x 64 rows x 144B @ 0, 9216
// W bufs: 2 x (<=64 rows x 144B) @ 18432, 27648
// GS: 64 x 34 floats @ 36864
#define SM_W 18432
#define SM_GS 36864
#define SMEM_BYTES (36864 + 64 * 34 * 4)

// -------- scratch --------
__device__ float g_pooled[Bq * DIN];
__device__ __half g_enc16[Bq * Hq];
__device__ float g_WT[Hq * NG];               // Wih0^T: [char][gate-row]
__device__ __half g_Wpk[512u * 32768u];       // 512 slices x 32 rows x 1024 (fp16)
__device__ __half g_Wout16[Hq * Hq];
__device__ __half g_h0h[Lq][Bq * Hq];         // h0 history
__device__ __half g_outs16[Lq * Bq * Hq];     // h1 history == layer-1 outputs
__device__ int g_fh0[Lq][4];
__device__ int g_fh1[Lq][4];

__device__ __forceinline__ float sigf(float x) { return 1.0f / (1.0f + __expf(-x)); }

__device__ __forceinline__ uint32_t h2_as_u32(__half2 h) {
    return *reinterpret_cast<uint32_t*>(&h);
}

__device__ __forceinline__ uint32_t s2u(const void* p) {
    uint32_t a;
    asm("{ .reg .u64 t; cvta.to.shared.u64 t, %1; cvt.u32.u64 %0, t; }" : "=r"(a) : "l"(p));
    return a;
}

__device__ __forceinline__ uint32_t f2tf32(float f) {
    uint32_t u;
    asm("cvt.rna.tf32.f32 %0, %1;" : "=r"(u) : "f"(f));
    return u;
}

__device__ __forceinline__ void ldsm_x4(uint32_t& r0, uint32_t& r1, uint32_t& r2, uint32_t& r3,
                                        uint32_t addr) {
    asm volatile("ldmatrix.sync.aligned.m8n8.x4.shared.b16 {%0,%1,%2,%3}, [%4];"
                 : "=r"(r0), "=r"(r1), "=r"(r2), "=r"(r3) : "r"(addr));
}

__device__ __forceinline__ void mma16816h(uint32_t& d0, uint32_t& d1,
                                          uint32_t a0, uint32_t a1, uint32_t a2, uint32_t a3,
                                          uint32_t b0, uint32_t b1) {
    asm volatile("mma.sync.aligned.m16n8k16.row.col.f16.f16.f16.f16 "
                 "{%0,%1}, {%2,%3,%4,%5}, {%6,%7}, {%0,%1};"
                 : "+r"(d0), "+r"(d1)
                 : "r"(a0), "r"(a1), "r"(a2), "r"(a3), "r"(b0), "r"(b1));
}

__device__ __forceinline__ void promo4(float* a4, uint32_t h0, uint32_t h1) {
    float2 lo = __half22float2(*reinterpret_cast<__half2*>(&h0));
    float2 hi = __half22float2(*reinterpret_cast<__half2*>(&h1));
    a4[0] += lo.x; a4[1] += lo.y; a4[2] += hi.x; a4[3] += hi.y;
}

__device__ __forceinline__ void mma_tf32(float& c0, float& c1, float& c2, float& c3,
                                         uint32_t a0, uint32_t a1, uint32_t a2, uint32_t a3,
                                         uint32_t b0, uint32_t b1) {
    asm volatile("mma.sync.aligned.m16n8k8.row.col.f32.tf32.tf32.f32 "
                 "{%0,%1,%2,%3}, {%4,%5,%6,%7}, {%8,%9}, {%0,%1,%2,%3};"
                 : "+f"(c0), "+f"(c1), "+f"(c2), "+f"(c3)
                 : "r"(a0), "r"(a1), "r"(a2), "r"(a3), "r"(b0), "r"(b1));
}

// wait until 4 sub-counters sum to 128 (called by tid 0, then __syncthreads)
__device__ __forceinline__ void waitf(const int* f) {
    int s;
    do {
        int a, b, c, d;
        asm volatile("ld.acquire.gpu.s32 %0,[%1];" : "=r"(a) : "l"(f));
        asm volatile("ld.acquire.gpu.s32 %0,[%1];" : "=r"(b) : "l"(f + 1));
        asm volatile("ld.acquire.gpu.s32 %0,[%1];" : "=r"(c) : "l"(f + 2));
        asm volatile("ld.acquire.gpu.s32 %0,[%1];" : "=r"(d) : "l"(f + 3));
        s = a + b + c + d;
    } while (s < 128);
}

__global__ void reset_kernel() {
    int i = blockIdx.x * blockDim.x + threadIdx.x;
    if (i < Lq * 4) {
        g_fh0[i >> 2][i & 3] = 0;
        g_fh1[i >> 2][i & 3] = 0;
    }
}

// -------- mean-pool audio --------
__global__ void pool_kernel(const float* __restrict__ audio) {
    int i = blockIdx.x * blockDim.x + threadIdx.x;
    int b = i / DIN, d = i % DIN;
    const float* p = audio + (size_t)b * TAUD * DIN + d;
    float s = 0.f;
#pragma unroll 5
    for (int t = 0; t < TAUD; t++) s += __ldcs(p + (size_t)t * DIN);
    g_pooled[i] = s * (1.0f / TAUD);
}

// -------- transpose Wih0 -> WT[char][gate-row] --------
__global__ void transpose_kernel(const float* __restrict__ W) {
    __shared__ float tile[32][33];
    int bx = blockIdx.x, by = blockIdx.y;
    int tx = threadIdx.x, ty0 = threadIdx.y;
#pragma unroll
    for (int q = 0; q < 4; q++) {
        int ty = ty0 + q * 8;
        tile[ty][tx] = W[(size_t)(by * 32 + ty) * Hq + bx * 32 + tx];
    }
    __syncthreads();
#pragma unroll
    for (int q = 0; q < 4; q++) {
        int ty = ty0 + q * 8;
        g_WT[(size_t)(bx * 32 + ty) * NG + by * 32 + tx] = tile[tx][ty];
    }
}

// -------- pack 512 fp16 W slices of 32 rows (8 units x 4 gates) --------
// sets: 0=Whh0, 1=Wih1, 2=Whh1, 3=Wih0;  slice row r: gate=r>>3, unit=j0+(r&7)
__global__ void pack_w16_kernel(const float* __restrict__ W0,
                                const float* __restrict__ W1,
                                const float* __restrict__ W2,
                                const float* __restrict__ W3) {
    int slice = blockIdx.x;          // 0..511
    int set = slice >> 7, blk = slice & 127;
    const float* W = (set == 0) ? W0 : (set == 1 ? W1 : (set == 2 ? W2 : W3));
    int j0 = blk * 8;
    __half* dst = g_Wpk + (size_t)slice * 32768;
    for (int f4 = threadIdx.x; f4 < 8192; f4 += 256) {
        int r = f4 >> 8;
        int c = (f4 & 255) * 4;
        int grow = (r >> 3) * Hq + j0 + (r & 7);
        float4 v = *(const float4*)(W + (size_t)grow * Hq + c);
        uint2 o;
        o.x = h2_as_u32(__floats2half2_rn(v.x, v.y));
        o.y = h2_as_u32(__floats2half2_rn(v.z, v.w));
        *(uint2*)(dst + (size_t)r * 1024 + c) = o;
    }
}

// -------- pack W_out to fp16 row-major --------
__global__ void pack_wout_kernel(const float* __restrict__ W) {
    int i = blockIdx.x * blockDim.x + threadIdx.x;
    float4 v = *(const float4*)(W + (size_t)i * 4);
    uint2 o;
    o.x = h2_as_u32(__floats2half2_rn(v.x, v.y));
    o.y = h2_as_u32(__floats2half2_rn(v.z, v.w));
    *(uint2*)(g_Wout16 + (size_t)i * 4) = o;
}

// ============ SIMT tf32 GEMM: enc = pooled @ W_proj^T + b -> fp16 ============
__global__ __launch_bounds__(256, 2)
void gemm_enc_kernel(const float* __restrict__ Bw,
                     const float* __restrict__ bias, int K) {
    __shared__ uint32_t As[64][36];
    __shared__ uint32_t Bs[64][36];
    const float* A = g_pooled;

    int tid = threadIdx.x;
    int lane = tid & 31, warp = tid >> 5;
    int nblk = blockIdx.x;
    int m0 = (warp & 3) * 16;
    int n0 = (warp >> 2) * 32;
    float acc[4][4] = {};
    int row = tid >> 3;
    int c4 = (tid & 7) * 4;

    const float* ap0 = A + (size_t)row * K + c4;
    const float* ap1 = A + (size_t)(row + 32) * K + c4;
    const float* bp0 = Bw + (size_t)(nblk * 64 + row) * K + c4;
    const float* bp1 = Bw + (size_t)(nblk * 64 + row + 32) * K + c4;

    int nC = K / 32;
    float4 xv0 = *(const float4*)ap0;
    float4 xv1 = *(const float4*)ap1;
    float4 wv0 = *(const float4*)bp0;
    float4 wv1 = *(const float4*)bp1;

    for (int c = 0; c < nC; c++) {
        uint4 u;
        u.x = f2tf32(xv0.x); u.y = f2tf32(xv0.y); u.z = f2tf32(xv0.z); u.w = f2tf32(xv0.w);
        *(uint4*)&As[row][c4] = u;
        u.x = f2tf32(xv1.x); u.y = f2tf32(xv1.y); u.z = f2tf32(xv1.z); u.w = f2tf32(xv1.w);
        *(uint4*)&As[row + 32][c4] = u;
        u.x = f2tf32(wv0.x); u.y = f2tf32(wv0.y); u.z = f2tf32(wv0.z); u.w = f2tf32(wv0.w);
        *(uint4*)&Bs[row][c4] = u;
        u.x = f2tf32(wv1.x); u.y = f2tf32(wv1.y); u.z = f2tf32(wv1.z); u.w = f2tf32(wv1.w);
        *(uint4*)&Bs[row + 32][c4] = u;
        __syncthreads();

        if (c + 1 < nC) {
            int k0 = (c + 1) * 32;
            xv0 = *(const float4*)(ap0 + k0);
            xv1 = *(const float4*)(ap1 + k0);
            wv0 = *(const float4*)(bp0 + k0);
            wv1 = *(const float4*)(bp1 + k0);
        }
#pragma unroll
        for (int ks = 0; ks < 4; ks++) {
            int kk = ks * 8;
            uint32_t a0 = As[m0 + (lane >> 2)][kk + (lane & 3)];
            uint32_t a1 = As[m0 + (lane >> 2) + 8][kk + (lane & 3)];
            uint32_t a2 = As[m0 + (lane >> 2)][kk + (lane & 3) + 4];
            uint32_t a3 = As[m0 + (lane >> 2) + 8][kk + (lane & 3) + 4];
#pragma unroll
            for (int nt = 0; nt < 4; nt++) {
                uint32_t b0 = Bs[n0 + nt * 8 + (lane >> 2)][kk + (lane & 3)];
                uint32_t b1 = Bs[n0 + nt * 8 + (lane >> 2)][kk + (lane & 3) + 4];
                mma_tf32(acc[nt][0], acc[nt][1], acc[nt][2], acc[nt][3],
                         a0, a1, a2, a3, b0, b1);
            }
        }
        __syncthreads();
    }

#pragma unroll
    for (int nt = 0; nt < 4; nt++) {
        int r = m0 + (lane >> 2);
        int cc = nblk * 64 + n0 + nt * 8 + (lane & 3) * 2;
        float bz0 = bias[cc], bz1 = bias[cc + 1];
        *(uint32_t*)&g_enc16[r * Hq + cc] =
            h2_as_u32(__floats2half2_rn(acc[nt][0] + bz0, acc[nt][1] + bz1));
        *(uint32_t*)&g_enc16[(r + 8) * Hq + cc] =
            h2_as_u32(__floats2half2_rn(acc[nt][2] + bz0, acc[nt][3] + bz1));
    }
}

// ============ persistent balanced LSTM + logits ============
// blocks 0..127: per iter s — H0(s) (N=32), then H1(s-1) (ih+hh, K=2048, N=32)
// blocks 128..143: logits stream, N=64 cols each
__global__ __launch_bounds__(256, 1)
void lstm_kernel(const float* __restrict__ bih0, const float* __restrict__ bhh0,
                 const float* __restrict__ bih1, const float* __restrict__ bhh1,
                 const float* __restrict__ b_out,
                 const int* __restrict__ text,
                 float* __restrict__ out) {
    extern __shared__ char smem[];
    const uint32_t sbase = s2u(smem);
    float* GS = (float*)(smem + SM_GS);

    const int tid = threadIdx.x;
    const int lane = tid & 31, warp = tid >> 5;
    const int gid = lane >> 2, tig = lane & 3;
    const int bid = blockIdx.x;

    const int xrow = tid >> 2, xc = (tid & 3) * 32;   // X loader: 64 rows, 2 uint4/thr
    const int mw = (warp & 3) * 16;

    if (bid < 128) {
        const int j0 = bid * 8;
        const int nw = (warp >> 2) * 16;
        const int wrow = tid >> 3, wc = (tid & 7) * 16;  // W loader: 32 rows, 1 uint4/thr
        const int u = lane & 7;
        const int mq0 = warp * 4 + (lane >> 3);          // m = mq0 + 32q
        const int j = j0 + u;

        float bs0[4], bs1[4];
        bs0[0] = bih0[j] + bhh0[j];
        bs0[1] = bih0[Hq + j] + bhh0[Hq + j];
        bs0[2] = bih0[2 * Hq + j] + bhh0[2 * Hq + j];
        bs0[3] = bih0[3 * Hq + j] + bhh0[3 * Hq + j];
        bs1[0] = bih1[j] + bhh1[j];
        bs1[1] = bih1[Hq + j] + bhh1[Hq + j];
        bs1[2] = bih1[2 * Hq + j] + bhh1[2 * Hq + j];
        bs1[3] = bih1[3 * Hq + j] + bhh1[3 * Hq + j];

        const char* wHH0 = (const char*)(g_Wpk + (size_t)(0 * 128 + bid) * 32768);
        const char* wIH1 = (const char*)(g_Wpk + (size_t)(1 * 128 + bid) * 32768);
        const char* wHH1 = (const char*)(g_Wpk + (size_t)(2 * 128 + bid) * 32768);
        const char* wIH0 = (const char*)(g_Wpk + (size_t)(3 * 128 + bid) * 32768);

        float c0[2] = {0.f, 0.f}, c1[2] = {0.f, 0.f};

        const char* Xp[2];
        const char* Wp[2];
        uint4 xv0, xv1, wv0;

        auto LDG = [&](int pass, int cc) {
            int cb = cc * 128;
            const char* xa = Xp[pass] + (size_t)xrow * 2048 + cb + xc;
            xv0 = __ldcg((const uint4*)xa);
            xv1 = __ldcg((const uint4*)(xa + 16));
            wv0 = *(const uint4*)(Wp[pass] + (size_t)wrow * 2048 + cb + wc);
        };
        auto STS = [&](int b) {
            char* xd = smem + b * 9216 + xrow * 144 + xc;
            *(uint4*)xd = xv0;
            *(uint4*)(xd + 16) = xv1;
            *(uint4*)(smem + SM_W + b * 9216 + wrow * 144 + wc) = wv0;
        };

        auto GEMM = [&](int nP) {   // result staged into GS[m*34 + n]
            float acc[2][4] = {};
            LDG(0, 0);
            STS(0);
            __syncthreads();
            int nC = nP * 16;
            for (int c = 0; c < nC; c++) {
                const int buf = c & 1;
                if (c + 1 < nC) LDG((c + 1) >> 4, (c + 1) & 15);
                const uint32_t xb = sbase + buf * 9216;
                const uint32_t wb = sbase + SM_W + buf * 9216;
                uint32_t hacc[2][2] = {};
#pragma unroll
                for (int ks = 0; ks < 4; ks++) {
                    int kh = ks * 16;
                    uint32_t a0, a1, a2, a3, b0, b1, b2, b3;
                    uint32_t ra = xb + (mw + (lane & 15)) * 144
                                + (kh + ((lane >> 4) << 3)) * 2;
                    ldsm_x4(a0, a1, a2, a3, ra);
                    uint32_t rb = wb + (nw + (lane & 7) + ((lane >> 4) << 3)) * 144
                                + (kh + (((lane >> 3) & 1) << 3)) * 2;
                    ldsm_x4(b0, b1, b2, b3, rb);
                    mma16816h(hacc[0][0], hacc[0][1], a0, a1, a2, a3, b0, b1);
                    mma16816h(hacc[1][0], hacc[1][1], a0, a1, a2, a3, b2, b3);
                }
                promo4(acc[0], hacc[0][0], hacc[0][1]);
                promo4(acc[1], hacc[1][0], hacc[1][1]);
                if (c + 1 < nC) STS(buf ^ 1);
                __syncthreads();
            }
            // stage to GS
#pragma unroll
            for (int nt = 0; nt < 2; nt++) {
                int m = mw + gid;
                int n = nw + nt * 8 + tig * 2;
                *(float2*)&GS[m * 34 + n] = make_float2(acc[nt][0], acc[nt][1]);
                *(float2*)&GS[(m + 8) * 34 + n] = make_float2(acc[nt][2], acc[nt][3]);
            }
            __syncthreads();
        };

        for (int s = 0; s <= 127; s++) {
            // ---------- H0(s) ----------
            if (s <= 126) {
                if (tid == 0 && s >= 1) waitf(g_fh0[s - 1]);
                __syncthreads();
                Xp[0] = (s == 0) ? (const char*)g_enc16 : (const char*)g_h0h[s - 1];
                Wp[0] = (s == 0) ? wIH0 : wHH0;
                GEMM(1);
                __half* hout = g_h0h[s];
#pragma unroll
                for (int q = 0; q < 2; q++) {
                    int m = mq0 + 32 * q;
                    float vi = GS[m * 34 + u] + bs0[0];
                    float vf = GS[m * 34 + 8 + u] + bs0[1];
                    float vg = GS[m * 34 + 16 + u] + bs0[2];
                    float vo = GS[m * 34 + 24 + u] + bs0[3];
                    if (s > 0) {
                        int ix = text[m * SEQLEN + s];
                        const float* wt = g_WT + (size_t)ix * NG;
                        vi += wt[j]; vf += wt[Hq + j];
                        vg += wt[2 * Hq + j]; vo += wt[3 * Hq + j];
                    }
                    float ig = sigf(vi), fg = sigf(vf), gg = tanhf(vg), og = sigf(vo);
                    float cn = fg * c0[q] + ig * gg;
                    c0[q] = cn;
                    hout[m * Hq + j] = __float2half(og * tanhf(cn));
                }
                __syncthreads();
                if (tid == 0) { __threadfence(); atomicAdd(&g_fh0[s][bid & 3], 1); }
            } else {
                if (tid == 0) waitf(g_fh0[126]);
                __syncthreads();
            }
            // ---------- H1(t = s-1) ----------
            if (s >= 1) {
                int t = s - 1;
                if (tid == 0 && t >= 1) waitf(g_fh1[t - 1]);
                __syncthreads();
                Xp[0] = (const char*)g_h0h[t];
                Wp[0] = wIH1;
                int nP = 1;
                if (t >= 1) {
                    Xp[1] = (const char*)(g_outs16 + (size_t)(t - 1) * Bq * Hq);
                    Wp[1] = wHH1;
                    nP = 2;
                }
                GEMM(nP);
                __half* hout = g_outs16 + (size_t)t * Bq * Hq;
#pragma unroll
                for (int q = 0; q < 2; q++) {
                    int m = mq0 + 32 * q;
                    float vi = GS[m * 34 + u] + bs1[0];
                    float vf = GS[m * 34 + 8 + u] + bs1[1];
                    float vg = GS[m * 34 + 16 + u] + bs1[2];
                    float vo = GS[m * 34 + 24 + u] + bs1[3];
                    float ig = sigf(vi), fg = sigf(vf), gg = tanhf(vg), og = sigf(vo);
                    float cn = fg * c1[q] + ig * gg;
                    c1[q] = cn;
                    hout[m * Hq + j] = __float2half(og * tanhf(cn));
                }
                __syncthreads();
                if (tid == 0) { __threadfence(); atomicAdd(&g_fh1[t][bid & 3], 1); }
            }
        }
    } else {
        // ---------- logits blocks ----------
        const int blkL = bid - 128;
        const int j0L = blkL * 64;
        const int nw2 = (warp >> 2) * 32;
        const char* Wsl = (const char*)(g_Wout16 + (size_t)j0L * 1024);
        float bz[4][2];
#pragma unroll
        for (int nt = 0; nt < 4; nt++) {
            int n = j0L + nw2 + nt * 8 + tig * 2;
            bz[nt][0] = b_out[n];
            bz[nt][1] = b_out[n + 1];
        }

        uint4 xv0, xv1, wv0, wv1;
        const char* Xp;
        auto LDG = [&](int cc) {
            int cb = cc * 128;
            const char* xa = Xp + (size_t)xrow * 2048 + cb + xc;
            xv0 = __ldcg((const uint4*)xa);
            xv1 = __ldcg((const uint4*)(xa + 16));
            const char* wa = Wsl + (size_t)xrow * 2048 + cb + xc;
            wv0 = *(const uint4*)wa;
            wv1 = *(const uint4*)(wa + 16);
        };
        auto STS = [&](int b) {
            char* xd = smem + b * 9216 + xrow * 144 + xc;
            *(uint4*)xd = xv0;
            *(uint4*)(xd + 16) = xv1;
            char* wd = smem + SM_W + b * 9216 + xrow * 144 + xc;
            *(uint4*)wd = wv0;
            *(uint4*)(wd + 16) = wv1;
        };

        for (int t = 0; t <= 126; t++) {
            if (tid == 0) waitf(g_fh1[t]);
            __syncthreads();
            Xp = (const char*)(g_outs16 + (size_t)t * Bq * Hq);
            float acc[4][4] = {};
            LDG(0);
            STS(0);
            __syncthreads();
            for (int c = 0; c < 16; c++) {
                const int buf = c & 1;
                if (c + 1 < 16) LDG(c + 1);
                const uint32_t xb = sbase + buf * 9216;
                const uint32_t wb = sbase + SM_W + buf * 9216;
                uint32_t hacc[4][2] = {};
#pragma unroll
                for (int ks = 0; ks < 4; ks++) {
                    int kh = ks * 16;
                    uint32_t a0, a1, a2, a3, b[2][4];
                    uint32_t ra = xb + (mw + (lane & 15)) * 144
                                + (kh + ((lane >> 4) << 3)) * 2;
                    ldsm_x4(a0, a1, a2, a3, ra);
#pragma unroll
                    for (int nt2 = 0; nt2 < 2; nt2++) {
                        uint32_t rb = wb + (nw2 + nt2 * 16 + (lane & 7) + ((lane >> 4) << 3)) * 144
                                    + (kh + (((lane >> 3) & 1) << 3)) * 2;
                        ldsm_x4(b[nt2][0], b[nt2][1], b[nt2][2], b[nt2][3], rb);
                    }
#pragma unroll
                    for (int nt = 0; nt < 4; nt++)
                        mma16816h(hacc[nt][0], hacc[nt][1], a0, a1, a2, a3,
                                  b[nt >> 1][(nt & 1) * 2], b[nt >> 1][(nt & 1) * 2 + 1]);
                }
#pragma unroll
                for (int nt = 0; nt < 4; nt++) promo4(acc[nt], hacc[nt][0], hacc[nt][1]);
                if (c + 1 < 16) STS(buf ^ 1);
                __syncthreads();
            }
#pragma unroll
            for (int nt = 0; nt < 4; nt++) {
                int n = j0L + nw2 + nt * 8 + tig * 2;
                int m = mw + gid;
                __stcs((float2*)&out[((size_t)m * Lq + t) * Hq + n],
                       make_float2(acc[nt][0] + bz[nt][0], acc[nt][1] + bz[nt][1]));
                __stcs((float2*)&out[((size_t)(m + 8) * Lq + t) * Hq + n],
                       make_float2(acc[nt][2] + bz[nt][0], acc[nt][3] + bz[nt][1]));
            }
            __syncthreads();
        }
    }
}

// -------- host launch --------
extern "C" void kernel_launch(void* const* d_in, const int* in_sizes, int n_in,
                              void* d_out, int out_size) {
    const float* audio  = (const float*)d_in[0];
    const int*   text   = (const int*)d_in[1];
    const float* W_proj = (const float*)d_in[2];
    const float* b_proj = (const float*)d_in[3];
    const float* W_ih0  = (const float*)d_in[4];
    const float* W_hh0  = (const float*)d_in[5];
    const float* b_ih0  = (const float*)d_in[6];
    const float* b_hh0  = (const float*)d_in[7];
    const float* W_ih1  = (const float*)d_in[8];
    const float* W_hh1  = (const float*)d_in[9];
    const float* b_ih1  = (const float*)d_in[10];
    const float* b_hh1  = (const float*)d_in[11];
    const float* W_out  = (const float*)d_in[12];
    const float* b_out  = (const float*)d_in[13];
    float* out = (float*)d_out;

    cudaFuncSetAttribute(lstm_kernel,
                         cudaFuncAttributeMaxDynamicSharedMemorySize, SMEM_BYTES);

    reset_kernel<<<2, 256>>>();
    pool_kernel<<<(Bq * DIN) / 128, 128>>>(audio);
    transpose_kernel<<<dim3(32, 128), dim3(32, 8)>>>(W_ih0);
    pack_w16_kernel<<<512, 256>>>(W_hh0, W_ih1, W_hh1, W_ih0);
    pack_wout_kernel<<<1024, 256>>>(W_out);
    gemm_enc_kernel<<<16, 256>>>(W_proj, b_proj, DIN);

    lstm_kernel<<<NPB, 256, SMEM_BYTES>>>(b_ih0, b_hh0, b_ih1, b_hh1,
                                          b_out, text, out);
}

// round 13
// speedup vs baseline: 1.3996x; 1.3996x over previous
#include <cuda_runtime.h>
#include <cuda_fp16.h>
#include <cstdint>

#define Bq 64
#define Hq 1024
#define NG 4096
#define DIN 768
#define TAUD 500
#define Lq 127
#define SEQLEN 128
#define NPB 224       // 64 G0 + 64 G1 + 64 G2 + 32 logits

// ---- dynamic smem (bytes): X 2x9216 | W 2x9216 | GS 64x66 f32 ----
#define SM_W 18432
#define SM_GS 36864
#define SMEM_BYTES (36864 + 64 * 66 * 4)   // 53760

// -------- scratch --------
__device__ float g_pooled[Bq * DIN];
__device__ __half g_enc16[Bq * Hq];
__device__ float g_WT[Hq * NG];                 // Wih0^T: [char][gate-row]
__device__ __half g_Wpk[256u * 65536u];         // 4 sets x 64 slices x 64 rows x 1024
__device__ __half g_Wout16[Hq * Hq];
__device__ __half g_h0h[Lq][Bq * Hq];           // h0 history (fp16)
__device__ __half g_outs16[Lq * Bq * Hq];       // h1 history == layer-1 outputs
__device__ float g_pih[2][Bq * NG];             // layer1 partial ih gates
__device__ int g_fh0[Lq][4];
__device__ int g_fpih[Lq][4];
__device__ int g_fh1[Lq][4];

__device__ __forceinline__ float sigf(float x) { return 1.0f / (1.0f + __expf(-x)); }

__device__ __forceinline__ uint32_t h2_as_u32(__half2 h) {
    return *reinterpret_cast<uint32_t*>(&h);
}

__device__ __forceinline__ uint32_t s2u(const void* p) {
    uint32_t a;
    asm("{ .reg .u64 t; cvta.to.shared.u64 t, %1; cvt.u32.u64 %0, t; }" : "=r"(a) : "l"(p));
    return a;
}

__device__ __forceinline__ uint32_t f2tf32(float f) {
    uint32_t u;
    asm("cvt.rna.tf32.f32 %0, %1;" : "=r"(u) : "f"(f));
    return u;
}

__device__ __forceinline__ void ldsm_x4(uint32_t& r0, uint32_t& r1, uint32_t& r2, uint32_t& r3,
                                        uint32_t addr) {
    asm volatile("ldmatrix.sync.aligned.m8n8.x4.shared.b16 {%0,%1,%2,%3}, [%4];"
                 : "=r"(r0), "=r"(r1), "=r"(r2), "=r"(r3) : "r"(addr));
}

__device__ __forceinline__ void mma16816h(uint32_t& d0, uint32_t& d1,
                                          uint32_t a0, uint32_t a1, uint32_t a2, uint32_t a3,
                                          uint32_t b0, uint32_t b1) {
    asm volatile("mma.sync.aligned.m16n8k16.row.col.f16.f16.f16.f16 "
                 "{%0,%1}, {%2,%3,%4,%5}, {%6,%7}, {%0,%1};"
                 : "+r"(d0), "+r"(d1)
                 : "r"(a0), "r"(a1), "r"(a2), "r"(a3), "r"(b0), "r"(b1));
}

__device__ __forceinline__ void promo4(float* a4, uint32_t h0, uint32_t h1) {
    float2 lo = __half22float2(*reinterpret_cast<__half2*>(&h0));
    float2 hi = __half22float2(*reinterpret_cast<__half2*>(&h1));
    a4[0] += lo.x; a4[1] += lo.y; a4[2] += hi.x; a4[3] += hi.y;
}

__device__ __forceinline__ void mma_tf32(float& c0, float& c1, float& c2, float& c3,
                                         uint32_t a0, uint32_t a1, uint32_t a2, uint32_t a3,
                                         uint32_t b0, uint32_t b1) {
    asm volatile("mma.sync.aligned.m16n8k8.row.col.f32.tf32.tf32.f32 "
                 "{%0,%1,%2,%3}, {%4,%5,%6,%7}, {%8,%9}, {%0,%1,%2,%3};"
                 : "+f"(c0), "+f"(c1), "+f"(c2), "+f"(c3)
                 : "r"(a0), "r"(a1), "r"(a2), "r"(a3), "r"(b0), "r"(b1));
}

// wait until 4 sub-counters sum to 64 (called by tid 0, then __syncthreads)
__device__ __forceinline__ void waitf(const int* f) {
    int s;
    do {
        int a, b, c, d;
        asm volatile("ld.acquire.gpu.s32 %0,[%1];" : "=r"(a) : "l"(f));
        asm volatile("ld.acquire.gpu.s32 %0,[%1];" : "=r"(b) : "l"(f + 1));
        asm volatile("ld.acquire.gpu.s32 %0,[%1];" : "=r"(c) : "l"(f + 2));
        asm volatile("ld.acquire.gpu.s32 %0,[%1];" : "=r"(d) : "l"(f + 3));
        s = a + b + c + d;
    } while (s < 64);
}

__global__ void reset_kernel() {
    int i = blockIdx.x * blockDim.x + threadIdx.x;
    if (i < Lq * 4) {
        ((int*)g_fh0)[i] = 0;
        ((int*)g_fpih)[i] = 0;
        ((int*)g_fh1)[i] = 0;
    }
}

// -------- mean-pool audio --------
__global__ void pool_kernel(const float* __restrict__ audio) {
    int i = blockIdx.x * blockDim.x + threadIdx.x;
    int b = i / DIN, d = i % DIN;
    const float* p = audio + (size_t)b * TAUD * DIN + d;
    float s = 0.f;
#pragma unroll 5
    for (int t = 0; t < TAUD; t++) s += __ldcs(p + (size_t)t * DIN);
    g_pooled[i] = s * (1.0f / TAUD);
}

// -------- transpose Wih0 -> WT[char][gate-row] --------
__global__ void transpose_kernel(const float* __restrict__ W) {
    __shared__ float tile[32][33];
    int bx = blockIdx.x, by = blockIdx.y;
    int tx = threadIdx.x, ty0 = threadIdx.y;
#pragma unroll
    for (int q = 0; q < 4; q++) {
        int ty = ty0 + q * 8;
        tile[ty][tx] = W[(size_t)(by * 32 + ty) * Hq + bx * 32 + tx];
    }
    __syncthreads();
#pragma unroll
    for (int q = 0; q < 4; q++) {
        int ty = ty0 + q * 8;
        g_WT[(size_t)(bx * 32 + ty) * NG + by * 32 + tx] = tile[tx][ty];
    }
}

// -------- pack fp16 W slices: 4 sets x 64 slices of 64 rows (16u x 4g) --------
// sets: 0=Whh0, 1=Wih1, 2=Whh1, 3=Wih0;  slice row r: gate=r>>4, unit=j0+(r&15)
__global__ void pack_w16_kernel(const float* __restrict__ W0,
                                const float* __restrict__ W1,
                                const float* __restrict__ W2,
                                const float* __restrict__ W3) {
    int id = blockIdx.x;              // 0..511
    int slice = id >> 1, half = id & 1;
    int set = slice >> 6, blkg = slice & 63;
    const float* W = (set == 0) ? W0 : (set == 1 ? W1 : (set == 2 ? W2 : W3));
    int j0 = blkg * 16;
    __half* dst = g_Wpk + (size_t)slice * 65536;
    int f4e = (half + 1) * 8192;
    for (int f4 = half * 8192 + threadIdx.x; f4 < f4e; f4 += 256) {
        int r = f4 >> 8;              // 0..63
        int c = (f4 & 255) * 4;
        int grow = (r >> 4) * Hq + j0 + (r & 15);
        float4 v = *(const float4*)(W + (size_t)grow * Hq + c);
        uint2 o;
        o.x = h2_as_u32(__floats2half2_rn(v.x, v.y));
        o.y = h2_as_u32(__floats2half2_rn(v.z, v.w));
        *(uint2*)(dst + (size_t)r * 1024 + c) = o;
    }
}

// -------- pack W_out to fp16 row-major --------
__global__ void pack_wout_kernel(const float* __restrict__ W) {
    int i = blockIdx.x * blockDim.x + threadIdx.x;
    float4 v = *(const float4*)(W + (size_t)i * 4);
    uint2 o;
    o.x = h2_as_u32(__floats2half2_rn(v.x, v.y));
    o.y = h2_as_u32(__floats2half2_rn(v.z, v.w));
    *(uint2*)(g_Wout16 + (size_t)i * 4) = o;
}

// ============ SIMT tf32 GEMM: enc = pooled @ W_proj^T + b -> fp16 ============
__global__ __launch_bounds__(256, 2)
void gemm_enc_kernel(const float* __restrict__ Bw,
                     const float* __restrict__ bias, int K) {
    __shared__ uint32_t As[64][36];
    __shared__ uint32_t Bs[64][36];
    const float* A = g_pooled;

    int tid = threadIdx.x;
    int lane = tid & 31, warp = tid >> 5;
    int nblk = blockIdx.x;
    int m0 = (warp & 3) * 16;
    int n0 = (warp >> 2) * 32;
    float acc[4][4] = {};
    int row = tid >> 3;
    int c4 = (tid & 7) * 4;

    const float* ap0 = A + (size_t)row * K + c4;
    const float* ap1 = A + (size_t)(row + 32) * K + c4;
    const float* bp0 = Bw + (size_t)(nblk * 64 + row) * K + c4;
    const float* bp1 = Bw + (size_t)(nblk * 64 + row + 32) * K + c4;

    int nC = K / 32;
    float4 xv0 = *(const float4*)ap0;
    float4 xv1 = *(const float4*)ap1;
    float4 wv0 = *(const float4*)bp0;
    float4 wv1 = *(const float4*)bp1;

    for (int c = 0; c < nC; c++) {
        uint4 u;
        u.x = f2tf32(xv0.x); u.y = f2tf32(xv0.y); u.z = f2tf32(xv0.z); u.w = f2tf32(xv0.w);
        *(uint4*)&As[row][c4] = u;
        u.x = f2tf32(xv1.x); u.y = f2tf32(xv1.y); u.z = f2tf32(xv1.z); u.w = f2tf32(xv1.w);
        *(uint4*)&As[row + 32][c4] = u;
        u.x = f2tf32(wv0.x); u.y = f2tf32(wv0.y); u.z = f2tf32(wv0.z); u.w = f2tf32(wv0.w);
        *(uint4*)&Bs[row][c4] = u;
        u.x = f2tf32(wv1.x); u.y = f2tf32(wv1.y); u.z = f2tf32(wv1.z); u.w = f2tf32(wv1.w);
        *(uint4*)&Bs[row + 32][c4] = u;
        __syncthreads();

        if (c + 1 < nC) {
            int k0 = (c + 1) * 32;
            xv0 = *(const float4*)(ap0 + k0);
            xv1 = *(const float4*)(ap1 + k0);
            wv0 = *(const float4*)(bp0 + k0);
            wv1 = *(const float4*)(bp1 + k0);
        }
#pragma unroll
        for (int ks = 0; ks < 4; ks++) {
            int kk = ks * 8;
            uint32_t a0 = As[m0 + (lane >> 2)][kk + (lane & 3)];
            uint32_t a1 = As[m0 + (lane >> 2) + 8][kk + (lane & 3)];
            uint32_t a2 = As[m0 + (lane >> 2)][kk + (lane & 3) + 4];
            uint32_t a3 = As[m0 + (lane >> 2) + 8][kk + (lane & 3) + 4];
#pragma unroll
            for (int nt = 0; nt < 4; nt++) {
                uint32_t b0 = Bs[n0 + nt * 8 + (lane >> 2)][kk + (lane & 3)];
                uint32_t b1 = Bs[n0 + nt * 8 + (lane >> 2)][kk + (lane & 3) + 4];
                mma_tf32(acc[nt][0], acc[nt][1], acc[nt][2], acc[nt][3],
                         a0, a1, a2, a3, b0, b1);
            }
        }
        __syncthreads();
    }

#pragma unroll
    for (int nt = 0; nt < 4; nt++) {
        int r = m0 + (lane >> 2);
        int cc = nblk * 64 + n0 + nt * 8 + (lane & 3) * 2;
        float bz0 = bias[cc], bz1 = bias[cc + 1];
        *(uint32_t*)&g_enc16[r * Hq + cc] =
            h2_as_u32(__floats2half2_rn(acc[nt][0] + bz0, acc[nt][1] + bz1));
        *(uint32_t*)&g_enc16[(r + 8) * Hq + cc] =
            h2_as_u32(__floats2half2_rn(acc[nt][2] + bz0, acc[nt][3] + bz1));
    }
}

// ============ persistent dataflow LSTM + logits; 128-thread CTAs, 2/SM ============
// [0,64)   G0: h0(s)            [64,128) G1: h1(s) finish (hh + pih)
// [128,192) G2: pih(s)          [192,224) G3: logits(s), N=32 cols
__global__ __launch_bounds__(128, 2)
void lstm_kernel(const float* __restrict__ bih0, const float* __restrict__ bhh0,
                 const float* __restrict__ bih1, const float* __restrict__ bhh1,
                 const float* __restrict__ b_out,
                 const int* __restrict__ text,
                 float* __restrict__ out) {
    extern __shared__ char smem[];
    const uint32_t sbase = s2u(smem);
    float* GS = (float*)(smem + SM_GS);

    const int tid = threadIdx.x;
    const int lane = tid & 31, warp = tid >> 5;
    const int gid = lane >> 2, tig = lane & 3;
    const int bid = blockIdx.x;
    const int xrow = tid >> 2, xi = tid & 3;
    const int mw = (warp & 1) * 32;

    if (bid < 192) {
        const int group = bid >> 6;          // 0=G0, 1=G1, 2=G2
        const int blkg = bid & 63;
        const int j0 = blkg * 16;
        const int nw = (warp >> 1) * 32;
        const int u = lane & 15;
        const int j = j0 + u;
        const int mq0 = warp + 4 * (lane >> 4);

        const int wset = (group == 0) ? 0 : (group == 1 ? 2 : 1);
        const char* wMain = (const char*)(g_Wpk + (size_t)(wset * 64 + blkg) * 65536);
        const char* wIH0  = (const char*)(g_Wpk + (size_t)(3 * 64 + blkg) * 65536);

        float bs[4] = {0.f, 0.f, 0.f, 0.f};
        if (group == 0) {
            bs[0] = bih0[j] + bhh0[j];
            bs[1] = bih0[Hq + j] + bhh0[Hq + j];
            bs[2] = bih0[2 * Hq + j] + bhh0[2 * Hq + j];
            bs[3] = bih0[3 * Hq + j] + bhh0[3 * Hq + j];
        } else if (group == 1) {
            bs[0] = bih1[j] + bhh1[j];
            bs[1] = bih1[Hq + j] + bhh1[Hq + j];
            bs[2] = bih1[2 * Hq + j] + bhh1[2 * Hq + j];
            bs[3] = bih1[3 * Hq + j] + bhh1[3 * Hq + j];
        }

        float creg[8];
#pragma unroll
        for (int q = 0; q < 8; q++) creg[q] = 0.f;

        for (int s = 0; s <= 126; s++) {
            if (tid == 0) {
                if (group == 0) {
                    if (s >= 1) waitf(g_fh0[s - 1]);
                } else if (group == 2) {
                    waitf(g_fh0[s]);
                    if (s >= 2) waitf(g_fh1[s - 2]);   // WAR on pih parity
                } else {
                    waitf(g_fpih[s]);
                    if (s >= 1) waitf(g_fh1[s - 1]);
                }
            }
            __syncthreads();

            const char* Xp = nullptr;
            const char* Wp = wMain;
            bool doGemm = true;
            if (group == 0) {
                if (s == 0) { Xp = (const char*)g_enc16; Wp = wIH0; }
                else Xp = (const char*)g_h0h[s - 1];
            } else if (group == 2) {
                Xp = (const char*)g_h0h[s];
            } else {
                doGemm = (s >= 1);
                if (doGemm) Xp = (const char*)(g_outs16 + (size_t)(s - 1) * Bq * Hq);
            }

            float acc[2][4][4] = {};
            if (doGemm) {
                uint4 xv[4], wv[4];
                auto LDG = [&](int cc) {
                    int cb = cc * 128;
                    const char* a = Xp + (size_t)xrow * 2048 + cb + xi * 32;
                    xv[0] = __ldcg((const uint4*)a);
                    xv[1] = __ldcg((const uint4*)(a + 16));
                    a = Xp + (size_t)(xrow + 32) * 2048 + cb + xi * 32;
                    xv[2] = __ldcg((const uint4*)a);
                    xv[3] = __ldcg((const uint4*)(a + 16));
                    const char* w = Wp + (size_t)xrow * 2048 + cb + xi * 32;
                    wv[0] = *(const uint4*)w;
                    wv[1] = *(const uint4*)(w + 16);
                    w = Wp + (size_t)(xrow + 32) * 2048 + cb + xi * 32;
                    wv[2] = *(const uint4*)w;
                    wv[3] = *(const uint4*)(w + 16);
                };
                auto STS = [&](int b) {
                    char* d = smem + b * 9216 + xrow * 144 + xi * 32;
                    *(uint4*)d = xv[0];
                    *(uint4*)(d + 16) = xv[1];
                    d = smem + b * 9216 + (xrow + 32) * 144 + xi * 32;
                    *(uint4*)d = xv[2];
                    *(uint4*)(d + 16) = xv[3];
                    d = smem + SM_W + b * 9216 + xrow * 144 + xi * 32;
                    *(uint4*)d = wv[0];
                    *(uint4*)(d + 16) = wv[1];
                    d = smem + SM_W + b * 9216 + (xrow + 32) * 144 + xi * 32;
                    *(uint4*)d = wv[2];
                    *(uint4*)(d + 16) = wv[3];
                };

                LDG(0);
                STS(0);
                __syncthreads();
                for (int c = 0; c < 16; c++) {
                    const int buf = c & 1;
                    if (c + 1 < 16) LDG(c + 1);
                    const uint32_t xb = sbase + buf * 9216;
                    const uint32_t wb = sbase + SM_W + buf * 9216;
                    uint32_t hacc[2][4][2] = {};
#pragma unroll
                    for (int ks = 0; ks < 4; ks++) {
                        int kh = ks * 16;
                        uint32_t a[2][4], b[2][4];
#pragma unroll
                        for (int ms = 0; ms < 2; ms++) {
                            uint32_t ra = xb + (mw + ms * 16 + (lane & 15)) * 144
                                        + (kh + ((lane >> 4) << 3)) * 2;
                            ldsm_x4(a[ms][0], a[ms][1], a[ms][2], a[ms][3], ra);
                        }
#pragma unroll
                        for (int nt2 = 0; nt2 < 2; nt2++) {
                            uint32_t rb = wb + (nw + nt2 * 16 + (lane & 7) + ((lane >> 4) << 3)) * 144
                                        + (kh + (((lane >> 3) & 1) << 3)) * 2;
                            ldsm_x4(b[nt2][0], b[nt2][1], b[nt2][2], b[nt2][3], rb);
                        }
#pragma unroll
                        for (int nt = 0; nt < 4; nt++) {
                            uint32_t b0 = b[nt >> 1][(nt & 1) * 2];
                            uint32_t b1 = b[nt >> 1][(nt & 1) * 2 + 1];
#pragma unroll
                            for (int ms = 0; ms < 2; ms++)
                                mma16816h(hacc[ms][nt][0], hacc[ms][nt][1],
                                          a[ms][0], a[ms][1], a[ms][2], a[ms][3], b0, b1);
                        }
                    }
#pragma unroll
                    for (int ms = 0; ms < 2; ms++)
#pragma unroll
                        for (int nt = 0; nt < 4; nt++)
                            promo4(acc[ms][nt], hacc[ms][nt][0], hacc[ms][nt][1]);
                    if (c + 1 < 16) STS(buf ^ 1);
                    __syncthreads();
                }
            }

            // stage gates into GS[m][n], n = gate*16 + u
#pragma unroll
            for (int ms = 0; ms < 2; ms++)
#pragma unroll
                for (int nt = 0; nt < 4; nt++)
#pragma unroll
                    for (int hh = 0; hh < 2; hh++) {
                        int m = mw + ms * 16 + gid + hh * 8;
                        int n = nw + nt * 8 + tig * 2;
                        *(float2*)&GS[m * 66 + n] =
                            make_float2(acc[ms][nt][hh * 2], acc[ms][nt][hh * 2 + 1]);
                    }
            __syncthreads();

            if (group == 2) {
                float* pout = g_pih[s & 1];
                for (int idx = tid; idx < 4096; idx += 128) {
                    int m = idx >> 6, gl = idx & 63;
                    int gn = (gl >> 4) * Hq + j0 + (gl & 15);
                    __stcg(&pout[(size_t)m * NG + gn], GS[m * 66 + gl]);
                }
            } else {
                __half* hout = (group == 0) ? g_h0h[s]
                                            : (g_outs16 + (size_t)s * Bq * Hq);
                const float* pin = (group == 1) ? g_pih[s & 1] : nullptr;
#pragma unroll
                for (int q = 0; q < 8; q++) {
                    int m = mq0 + 8 * q;
                    float vi = GS[m * 66 + u] + bs[0];
                    float vf = GS[m * 66 + 16 + u] + bs[1];
                    float vg = GS[m * 66 + 32 + u] + bs[2];
                    float vo = GS[m * 66 + 48 + u] + bs[3];
                    if (group == 0) {
                        if (s > 0) {
                            int ix = text[m * SEQLEN + s];
                            const float* wt = g_WT + (size_t)ix * NG;
                            vi += wt[j]; vf += wt[Hq + j];
                            vg += wt[2 * Hq + j]; vo += wt[3 * Hq + j];
                        }
                    } else {
                        const float* pm = pin + (size_t)m * NG;
                        vi += __ldcg(&pm[j]); vf += __ldcg(&pm[Hq + j]);
                        vg += __ldcg(&pm[2 * Hq + j]); vo += __ldcg(&pm[3 * Hq + j]);
                    }
                    float ig = sigf(vi), fg = sigf(vf), gg = tanhf(vg), og = sigf(vo);
                    float cn = fg * creg[q] + ig * gg;
                    creg[q] = cn;
                    hout[m * Hq + j] = __float2half(og * tanhf(cn));
                }
            }
            __syncthreads();

            if (tid == 0) {
                __threadfence();
                if (group == 0) atomicAdd(&g_fh0[s][bid & 3], 1);
                else if (group == 2) atomicAdd(&g_fpih[s][bid & 3], 1);
                else atomicAdd(&g_fh1[s][bid & 3], 1);
            }
        }
    } else {
        // ---------- logits: 32 CTAs, N=32 cols, M=64, K=1024 ----------
        const int blkL = bid - 192;
        const int j0L = blkL * 32;
        const int nw2 = (warp >> 1) * 16;
        const char* Wsl = (const char*)(g_Wout16 + (size_t)j0L * 1024);
        float bz[2][2];
#pragma unroll
        for (int nt = 0; nt < 2; nt++) {
            int n = j0L + nw2 + nt * 8 + tig * 2;
            bz[nt][0] = b_out[n];
            bz[nt][1] = b_out[n + 1];
        }

        for (int t = 0; t <= 126; t++) {
            if (tid == 0) waitf(g_fh1[t]);
            __syncthreads();
            const char* Xp = (const char*)(g_outs16 + (size_t)t * Bq * Hq);

            float acc[2][2][4] = {};
            uint4 xv[4], wv[2];
            auto LDG = [&](int cc) {
                int cb = cc * 128;
                const char* a = Xp + (size_t)xrow * 2048 + cb + xi * 32;
                xv[0] = __ldcg((const uint4*)a);
                xv[1] = __ldcg((const uint4*)(a + 16));
                a = Xp + (size_t)(xrow + 32) * 2048 + cb + xi * 32;
                xv[2] = __ldcg((const uint4*)a);
                xv[3] = __ldcg((const uint4*)(a + 16));
                const char* w = Wsl + (size_t)xrow * 2048 + cb + xi * 32;
                wv[0] = *(const uint4*)w;
                wv[1] = *(const uint4*)(w + 16);
            };
            auto STS = [&](int b) {
                char* d = smem + b * 9216 + xrow * 144 + xi * 32;
                *(uint4*)d = xv[0];
                *(uint4*)(d + 16) = xv[1];
                d = smem + b * 9216 + (xrow + 32) * 144 + xi * 32;
                *(uint4*)d = xv[2];
                *(uint4*)(d + 16) = xv[3];
                d = smem + SM_W + b * 9216 + xrow * 144 + xi * 32;
                *(uint4*)d = wv[0];
                *(uint4*)(d + 16) = wv[1];
            };
            LDG(0);
            STS(0);
            __syncthreads();
            for (int c = 0; c < 16; c++) {
                const int buf = c & 1;
                if (c + 1 < 16) LDG(c + 1);
                const uint32_t xb = sbase + buf * 9216;
                const uint32_t wb = sbase + SM_W + buf * 9216;
                uint32_t hacc[2][2][2] = {};
#pragma unroll
                for (int ks = 0; ks < 4; ks++) {
                    int kh = ks * 16;
                    uint32_t a[2][4], b[4];
#pragma unroll
                    for (int ms = 0; ms < 2; ms++) {
                        uint32_t ra = xb + (mw + ms * 16 + (lane & 15)) * 144
                                    + (kh + ((lane >> 4) << 3)) * 2;
                        ldsm_x4(a[ms][0], a[ms][1], a[ms][2], a[ms][3], ra);
                    }
                    uint32_t rb = wb + (nw2 + (lane & 7) + ((lane >> 4) << 3)) * 144
                                + (kh + (((lane >> 3) & 1) << 3)) * 2;
                    ldsm_x4(b[0], b[1], b[2], b[3], rb);
#pragma unroll
                    for (int nt = 0; nt < 2; nt++)
#pragma unroll
                        for (int ms = 0; ms < 2; ms++)
                            mma16816h(hacc[ms][nt][0], hacc[ms][nt][1],
                                      a[ms][0], a[ms][1], a[ms][2], a[ms][3],
                                      b[nt * 2], b[nt * 2 + 1]);
                }
#pragma unroll
                for (int ms = 0; ms < 2; ms++)
#pragma unroll
                    for (int nt = 0; nt < 2; nt++)
                        promo4(acc[ms][nt], hacc[ms][nt][0], hacc[ms][nt][1]);
                if (c + 1 < 16) STS(buf ^ 1);
                __syncthreads();
            }
#pragma unroll
            for (int ms = 0; ms < 2; ms++)
#pragma unroll
                for (int nt = 0; nt < 2; nt++) {
                    int n = j0L + nw2 + nt * 8 + tig * 2;
                    int m = mw + ms * 16 + gid;
                    __stcs((float2*)&out[((size_t)m * Lq + t) * Hq + n],
                           make_float2(acc[ms][nt][0] + bz[nt][0],
                                       acc[ms][nt][1] + bz[nt][1]));
                    __stcs((float2*)&out[((size_t)(m + 8) * Lq + t) * Hq + n],
                           make_float2(acc[ms][nt][2] + bz[nt][0],
                                       acc[ms][nt][3] + bz[nt][1]));
                }
            __syncthreads();
        }
    }
}

// -------- host launch --------
extern "C" void kernel_launch(void* const* d_in, const int* in_sizes, int n_in,
                              void* d_out, int out_size) {
    const float* audio  = (const float*)d_in[0];
    const int*   text   = (const int*)d_in[1];
    const float* W_proj = (const float*)d_in[2];
    const float* b_proj = (const float*)d_in[3];
    const float* W_ih0  = (const float*)d_in[4];
    const float* W_hh0  = (const float*)d_in[5];
    const float* b_ih0  = (const float*)d_in[6];
    const float* b_hh0  = (const float*)d_in[7];
    const float* W_ih1  = (const float*)d_in[8];
    const float* W_hh1  = (const float*)d_in[9];
    const float* b_ih1  = (const float*)d_in[10];
    const float* b_hh1  = (const float*)d_in[11];
    const float* W_out  = (const float*)d_in[12];
    const float* b_out  = (const float*)d_in[13];
    float* out = (float*)d_out;

    cudaFuncSetAttribute(lstm_kernel,
                         cudaFuncAttributeMaxDynamicSharedMemorySize, SMEM_BYTES);

    reset_kernel<<<2, 256>>>();
    pool_kernel<<<(Bq * DIN) / 128, 128>>>(audio);
    transpose_kernel<<<dim3(32, 128), dim3(32, 8)>>>(W_ih0);
    pack_w16_kernel<<<512, 256>>>(W_hh0, W_ih1, W_hh1, W_ih0);
    pack_wout_kernel<<<1024, 256>>>(W_out);
    gemm_enc_kernel<<<16, 256>>>(W_proj, b_proj, DIN);

    lstm_kernel<<<NPB, 128, SMEM_BYTES>>>(b_ih0, b_hh0, b_ih1, b_hh1,
                                          b_out, text, out);
}